// round 16
// baseline (speedup 1.0000x reference)
#include <cuda_runtime.h>

#define C_DIM 256
#define H_DIM 200
#define W_DIM 336
#define OUT_HW 7
#define NS 2
#define SCALE 0.25f

__global__ void __launch_bounds__(256) roi_align_kernel(
    const float* __restrict__ feats,   // (B, C, H, W)
    const float* __restrict__ rois,    // (N, 5)
    float* __restrict__ out,           // (N, C, 7, 7)
    int total)
{
    int idx = blockIdx.x * blockDim.x + threadIdx.x;
    if (idx >= total) return;

    // out layout: ((n*C + c)*7 + ph)*7 + pw  -> pw fastest (coalesced writes)
    int pw = idx % OUT_HW;
    int t1 = idx / OUT_HW;
    int ph = t1 % OUT_HW;
    int t2 = t1 / OUT_HW;
    int c  = t2 % C_DIM;
    int n  = t2 / C_DIM;

    const float* r = rois + (size_t)n * 5;
    int   b  = (int)__ldg(r + 0);
    float x1 = __ldg(r + 1) * SCALE;
    float y1 = __ldg(r + 2) * SCALE;
    float x2 = __ldg(r + 3) * SCALE;
    float y2 = __ldg(r + 4) * SCALE;

    float roi_w = fmaxf(x2 - x1, 1.0f);
    float roi_h = fmaxf(y2 - y1, 1.0f);
    // bin / ns step sizes
    float sx = roi_w * (1.0f / (OUT_HW * NS));   // bin_w / ns
    float sy = roi_h * (1.0f / (OUT_HW * NS));   // bin_h / ns

    const float* fptr = feats + ((size_t)b * C_DIM + c) * (H_DIM * W_DIM);

    float acc = 0.0f;

    #pragma unroll
    for (int iy = 0; iy < NS; iy++) {
        // sample row index p = ph*ns + iy ; ys = y1 + (p + 0.5) * sy
        float yy = y1 + ((float)(ph * NS + iy) + 0.5f) * sy;
        bool ymask = (yy >= -1.0f) && (yy <= (float)H_DIM);
        float y  = fminf(fmaxf(yy, 0.0f), (float)(H_DIM - 1));
        int   y0 = (int)floorf(y);
        int   y1i = min(y0 + 1, H_DIM - 1);
        float ly = y - (float)y0;
        float hy = 1.0f - ly;
        const float* row0 = fptr + (size_t)y0  * W_DIM;
        const float* row1 = fptr + (size_t)y1i * W_DIM;

        #pragma unroll
        for (int ix = 0; ix < NS; ix++) {
            float xx = x1 + ((float)(pw * NS + ix) + 0.5f) * sx;
            bool xmask = (xx >= -1.0f) && (xx <= (float)W_DIM);
            float x  = fminf(fmaxf(xx, 0.0f), (float)(W_DIM - 1));
            int   x0 = (int)floorf(x);
            int   x1i = min(x0 + 1, W_DIM - 1);
            float lx = x - (float)x0;
            float hx = 1.0f - lx;

            float f00 = __ldg(row0 + x0);
            float f01 = __ldg(row0 + x1i);
            float f10 = __ldg(row1 + x0);
            float f11 = __ldg(row1 + x1i);

            float v = hy * fmaf(hx, f00, lx * f01) + ly * fmaf(hx, f10, lx * f11);
            if (ymask && xmask) acc += v;
        }
    }

    out[idx] = acc * (1.0f / (NS * NS));
}

extern "C" void kernel_launch(void* const* d_in, const int* in_sizes, int n_in,
                              void* d_out, int out_size)
{
    const float* feats = (const float*)d_in[0];
    const float* rois  = (const float*)d_in[1];
    float* out = (float*)d_out;

    int total = out_size;  // N * C * 7 * 7
    int threads = 256;
    int blocks = (total + threads - 1) / threads;
    roi_align_kernel<<<blocks, threads>>>(feats, rois, out, total);
}

// round 17
// speedup vs baseline: 1.0014x; 1.0014x over previous
#include <cuda_runtime.h>

#define C_DIM 256
#define H_DIM 200
#define W_DIM 336
#define OUT_HW 7
#define NS 2
#define SCALE 0.25f

__global__ void __launch_bounds__(256) roi_align_kernel(
    const float* __restrict__ feats,   // (B, C, H, W)
    const float* __restrict__ rois,    // (N, 5)
    float* __restrict__ out,           // (N, C, 7, 7)
    int total)
{
    int idx = blockIdx.x * blockDim.x + threadIdx.x;
    if (idx >= total) return;

    // out layout: ((n*C + c)*7 + ph)*7 + pw  -> pw fastest (coalesced writes)
    int pw = idx % OUT_HW;
    int t1 = idx / OUT_HW;
    int ph = t1 % OUT_HW;
    int t2 = t1 / OUT_HW;
    int c  = t2 % C_DIM;
    int n  = t2 / C_DIM;

    const float* r = rois + (size_t)n * 5;
    int   b  = (int)__ldg(r + 0);
    float x1 = __ldg(r + 1) * SCALE;
    float y1 = __ldg(r + 2) * SCALE;
    float x2 = __ldg(r + 3) * SCALE;
    float y2 = __ldg(r + 4) * SCALE;

    float roi_w = fmaxf(x2 - x1, 1.0f);
    float roi_h = fmaxf(y2 - y1, 1.0f);
    // bin / ns step sizes
    float sx = roi_w * (1.0f / (OUT_HW * NS));   // bin_w / ns
    float sy = roi_h * (1.0f / (OUT_HW * NS));   // bin_h / ns

    const float* fptr = feats + ((size_t)b * C_DIM + c) * (H_DIM * W_DIM);

    float acc = 0.0f;

    #pragma unroll
    for (int iy = 0; iy < NS; iy++) {
        // sample row index p = ph*ns + iy ; ys = y1 + (p + 0.5) * sy
        float yy = y1 + ((float)(ph * NS + iy) + 0.5f) * sy;
        bool ymask = (yy >= -1.0f) && (yy <= (float)H_DIM);
        float y  = fminf(fmaxf(yy, 0.0f), (float)(H_DIM - 1));
        int   y0 = (int)floorf(y);
        int   y1i = min(y0 + 1, H_DIM - 1);
        float ly = y - (float)y0;
        float hy = 1.0f - ly;
        const float* row0 = fptr + (size_t)y0  * W_DIM;
        const float* row1 = fptr + (size_t)y1i * W_DIM;

        #pragma unroll
        for (int ix = 0; ix < NS; ix++) {
            float xx = x1 + ((float)(pw * NS + ix) + 0.5f) * sx;
            bool xmask = (xx >= -1.0f) && (xx <= (float)W_DIM);
            float x  = fminf(fmaxf(xx, 0.0f), (float)(W_DIM - 1));
            int   x0 = (int)floorf(x);
            int   x1i = min(x0 + 1, W_DIM - 1);
            float lx = x - (float)x0;
            float hx = 1.0f - lx;

            float f00 = __ldg(row0 + x0);
            float f01 = __ldg(row0 + x1i);
            float f10 = __ldg(row1 + x0);
            float f11 = __ldg(row1 + x1i);

            float v = hy * fmaf(hx, f00, lx * f01) + ly * fmaf(hx, f10, lx * f11);
            if (ymask && xmask) acc += v;
        }
    }

    out[idx] = acc * (1.0f / (NS * NS));
}

extern "C" void kernel_launch(void* const* d_in, const int* in_sizes, int n_in,
                              void* d_out, int out_size)
{
    const float* feats = (const float*)d_in[0];
    const float* rois  = (const float*)d_in[1];
    float* out = (float*)d_out;

    int total = out_size;  // N * C * 7 * 7
    int threads = 256;
    int blocks = (total + threads - 1) / threads;
    roi_align_kernel<<<blocks, threads>>>(feats, rois, out, total);
}